// round 2
// baseline (speedup 1.0000x reference)
#include <cuda_runtime.h>
#include <cstdint>
#include <cstddef>

// GRU: T=512, B=64, H=1024, I=1024, fp32.
// Node 1-3: xproj GEMMs (x @ Wg[:,H:]^T + bias) into g_xp.
// Node 4: persistent kernel, 128 CTAs, software grid barriers, 512 steps:
//   Phase A: z = sigmoid(h@Wz[:,:H]^T + xpz); r = sigmoid(h@Wr[:,:H]^T + xpr); rhT = r*h (transposed)
//   Phase B: h~ = tanh(rh@Wt[:,:H]^T + xpt); h = h + z*(h~-h) -> out[t] and hT.

#define TT 512
#define BB 64
#define HH 1024
#define II 1024
#define HIW 2048
#define BHN (BB * HH)            // 65536
#define TBH ((size_t)TT * BHN)
#define NCTA 128
#define NTHR 256

typedef unsigned long long ull;

__device__ float g_xp[3][TBH];   // 402 MB x-projections (+bias)
__device__ float g_hT[HH * BB];  // h transposed [n][b]
__device__ float g_rhT[HH * BB]; // r*h transposed [n][b]
__device__ float g_z[BB * HH];   // z gate [b][n]
__device__ unsigned g_cnt;
__device__ unsigned g_gen;

// ---- packed fp32x2 helpers ----
__device__ __forceinline__ ull pk2(float lo, float hi) {
    ull r; asm("mov.b64 %0, {%1, %2};" : "=l"(r) : "f"(lo), "f"(hi)); return r;
}
__device__ __forceinline__ void upk2(ull v, float& lo, float& hi) {
    asm("mov.b64 {%0, %1}, %2;" : "=f"(lo), "=f"(hi) : "l"(v));
}
__device__ __forceinline__ void fma2(ull& d, ull a, ull b) {
    asm("fma.rn.f32x2 %0, %1, %2, %0;" : "+l"(d) : "l"(a), "l"(b));
}
__device__ __forceinline__ float sigmoidf_fast(float v) {
    return 1.0f / (1.0f + __expf(-v));
}

// Grid-wide sense barrier. All threads fence (release + L1D invalidate on acquire).
__device__ __forceinline__ void gbar() {
    __threadfence();
    __syncthreads();
    if (threadIdx.x == 0) {
        unsigned my = *(volatile unsigned*)&g_gen;
        if (atomicAdd(&g_cnt, 1) == NCTA - 1) {
            g_cnt = 0;
            __threadfence();
            *(volatile unsigned*)&g_gen = my + 1;
        } else {
            while (*(volatile unsigned*)&g_gen == my) { }
        }
    }
    __syncthreads();
    __threadfence();   // acquire; CCTL.IVALL flushes this SM's L1D
}

// ============================================================================
// Phase 1: xproj. C[m,n] = bias[n] + sum_k x[m,k]*W[n,H+k]. M=32768,N=1024,K=1024
// BM=128, BN=64, BK=16, 256 threads, thread tile 8x4.
// ============================================================================
__global__ __launch_bounds__(256) void xproj_kernel(
    const float* __restrict__ x, const float* __restrict__ W,
    const float* __restrict__ bias, int gate)
{
    __shared__ float As[16][132];
    __shared__ float Bs[16][68];

    const int tid = threadIdx.x;
    const int tn = tid & 15;
    const int tm = tid >> 4;
    const int m0 = blockIdx.x * 128;
    const int n0 = blockIdx.y * 64;
    float* __restrict__ out = g_xp[gate];

    ull acc[4][4];
#pragma unroll
    for (int i = 0; i < 4; i++)
#pragma unroll
        for (int j = 0; j < 4; j++) acc[i][j] = 0ull;

    for (int k0 = 0; k0 < II; k0 += 16) {
#pragma unroll
        for (int r = 0; r < 2; r++) {
            int idx = tid + r * 256;
            int mm = idx >> 2;
            int kq = idx & 3;
            float4 v = *(const float4*)(x + (size_t)(m0 + mm) * II + k0 + kq * 4);
            As[kq * 4 + 0][mm] = v.x; As[kq * 4 + 1][mm] = v.y;
            As[kq * 4 + 2][mm] = v.z; As[kq * 4 + 3][mm] = v.w;
        }
        {
            int nn = tid >> 2;
            int kq = tid & 3;
            float4 v = *(const float4*)(W + (size_t)(n0 + nn) * HIW + HH + k0 + kq * 4);
            Bs[kq * 4 + 0][nn] = v.x; Bs[kq * 4 + 1][nn] = v.y;
            Bs[kq * 4 + 2][nn] = v.z; Bs[kq * 4 + 3][nn] = v.w;
        }
        __syncthreads();

#pragma unroll
        for (int k = 0; k < 16; k++) {
            float4 a0 = *(const float4*)&As[k][tm * 8];
            float4 a1 = *(const float4*)&As[k][tm * 8 + 4];
            float4 b  = *(const float4*)&Bs[k][tn * 4];
            ull ap[4];
            ap[0] = pk2(a0.x, a0.y); ap[1] = pk2(a0.z, a0.w);
            ap[2] = pk2(a1.x, a1.y); ap[3] = pk2(a1.z, a1.w);
            ull bs[4];
            bs[0] = pk2(b.x, b.x); bs[1] = pk2(b.y, b.y);
            bs[2] = pk2(b.z, b.z); bs[3] = pk2(b.w, b.w);
#pragma unroll
            for (int rp = 0; rp < 4; rp++)
#pragma unroll
                for (int c = 0; c < 4; c++) fma2(acc[rp][c], ap[rp], bs[c]);
        }
        __syncthreads();
    }

    const float b0 = bias[n0 + tn * 4 + 0];
    const float b1 = bias[n0 + tn * 4 + 1];
    const float b2 = bias[n0 + tn * 4 + 2];
    const float b3 = bias[n0 + tn * 4 + 3];
#pragma unroll
    for (int rp = 0; rp < 4; rp++) {
        float lo[4], hi[4];
#pragma unroll
        for (int c = 0; c < 4; c++) upk2(acc[rp][c], lo[c], hi[c]);
        int row = m0 + tm * 8 + rp * 2;
        float4 vlo = make_float4(lo[0] + b0, lo[1] + b1, lo[2] + b2, lo[3] + b3);
        float4 vhi = make_float4(hi[0] + b0, hi[1] + b1, hi[2] + b2, hi[3] + b3);
        *(float4*)(out + (size_t)row * HH + n0 + tn * 4) = vlo;
        *(float4*)(out + (size_t)(row + 1) * HH + n0 + tn * 4) = vhi;
    }
}

// ============================================================================
// Persistent recurrence kernel. 128 CTAs x 256 threads, 1 CTA/SM.
// Dynamic smem: sWA [1024][16] (64KB) | sWB [1024][8] (32KB) | sred 73728B
// Phase A: CTA<64 -> z cols cta*16..; CTA>=64 -> r cols (cta-64)*16..
//   thread: s=tid>>4 (16 k-slices), cg=(tid>>3)&1 (col half), rg=tid&7 (8-row grp)
//   k = j*16 + s, j=0..63. Tile 8 rows x 8 cols. Reduce 16 partials in smem.
// Phase B: cols cta*8.. ; s=tid>>3 (32 slices), rg=tid&7; k=j*32+s, j=0..31.
// ============================================================================
__global__ __launch_bounds__(NTHR, 1) void gru_persist(
    const float* __restrict__ h0,
    const float* __restrict__ Wz, const float* __restrict__ Wr,
    const float* __restrict__ Wt, float* __restrict__ out)
{
    extern __shared__ float sm[];
    float* sWA  = sm;            // 16384 floats
    float* sWB  = sm + 16384;    // 8192 floats
    float* sred = sm + 24576;    // 18432 floats

    const int tid = threadIdx.x;
    const int cta = blockIdx.x;

    // ---- one-time: load recurrent weight stripes into smem (coalesced in k) ----
    {
        const float* Wsrc = (cta < 64) ? Wz : Wr;
        const int c0 = (cta & 63) * 16;
#pragma unroll 1
        for (int c = 0; c < 16; c++)
            for (int k = tid; k < HH; k += NTHR)
                sWA[k * 16 + c] = Wsrc[(size_t)(c0 + c) * HIW + k];
        const int c0b = cta * 8;
#pragma unroll 1
        for (int c = 0; c < 8; c++)
            for (int k = tid; k < HH; k += NTHR)
                sWB[k * 8 + c] = Wt[(size_t)(c0b + c) * HIW + k];
    }
    // ---- one-time: transpose h0 into g_hT ----
    for (int i = cta * NTHR + tid; i < BHN; i += NCTA * NTHR) {
        int b = i >> 10, n = i & 1023;
        g_hT[n * BB + b] = h0[i];
    }
    __syncthreads();
    gbar();

    const int sA = tid >> 4, cgA = (tid >> 3) & 1, rgA = tid & 7;
    const int sB = tid >> 3, rgB = tid & 7;
    const int ocA = tid & 15; const int obA = (tid >> 4) * 4;
    const int ocB = tid & 7;  const int obB = (tid >> 3) * 2;
    const int gate = (cta < 64) ? 0 : 1;
    const int nbaseA = (cta & 63) * 16;
    const int nbaseB = cta * 8;

    for (int t = 0; t < TT; t++) {
        // ================= Phase A =================
        {
            ull acc[4][8];
#pragma unroll
            for (int i = 0; i < 4; i++)
#pragma unroll
                for (int j = 0; j < 8; j++) acc[i][j] = 0ull;

#pragma unroll 4
            for (int j = 0; j < 64; j++) {
                const int k = j * 16 + sA;
                float4 ha = __ldcg((const float4*)(g_hT + k * BB + rgA * 8));
                float4 hb = __ldcg((const float4*)(g_hT + k * BB + rgA * 8 + 4));
                float4 w0 = *(const float4*)&sWA[k * 16 + cgA * 8];
                float4 w1 = *(const float4*)&sWA[k * 16 + cgA * 8 + 4];
                ull hp[4];
                hp[0] = pk2(ha.x, ha.y); hp[1] = pk2(ha.z, ha.w);
                hp[2] = pk2(hb.x, hb.y); hp[3] = pk2(hb.z, hb.w);
                ull wd[8];
                wd[0] = pk2(w0.x, w0.x); wd[1] = pk2(w0.y, w0.y);
                wd[2] = pk2(w0.z, w0.z); wd[3] = pk2(w0.w, w0.w);
                wd[4] = pk2(w1.x, w1.x); wd[5] = pk2(w1.y, w1.y);
                wd[6] = pk2(w1.z, w1.z); wd[7] = pk2(w1.w, w1.w);
#pragma unroll
                for (int rp = 0; rp < 4; rp++)
#pragma unroll
                    for (int c = 0; c < 8; c++) fma2(acc[rp][c], hp[rp], wd[c]);
            }
            // write partials
#pragma unroll
            for (int rp = 0; rp < 4; rp++) {
                int b0 = rgA * 8 + rp * 2;
#pragma unroll
                for (int c = 0; c < 8; c++) {
                    float lo, hi; upk2(acc[rp][c], lo, hi);
                    sred[sA * 1152 + b0 * 18 + cgA * 8 + c] = lo;
                    sred[sA * 1152 + (b0 + 1) * 18 + cgA * 8 + c] = hi;
                }
            }
            __syncthreads();
            // reduce 16 partials + epilogue (4 outputs/thread)
            const float* __restrict__ xpg = g_xp[gate] + (size_t)t * BHN;
            const int n = nbaseA + ocA;
#pragma unroll
            for (int bi = 0; bi < 4; bi++) {
                const int bb = obA + bi;
                float v = 0.0f;
#pragma unroll
                for (int s = 0; s < 16; s++) v += sred[s * 1152 + bb * 18 + ocA];
                v += xpg[bb * HH + n];
                float sg = sigmoidf_fast(v);
                if (gate == 0) {
                    g_z[bb * HH + n] = sg;
                } else {
                    float hp = __ldcg(&g_hT[n * BB + bb]);
                    g_rhT[n * BB + bb] = sg * hp;
                }
            }
        }
        gbar();

        // ================= Phase B =================
        {
            ull acc[4][8];
#pragma unroll
            for (int i = 0; i < 4; i++)
#pragma unroll
                for (int j = 0; j < 8; j++) acc[i][j] = 0ull;

#pragma unroll 4
            for (int j = 0; j < 32; j++) {
                const int k = j * 32 + sB;
                float4 ha = __ldcg((const float4*)(g_rhT + k * BB + rgB * 8));
                float4 hb = __ldcg((const float4*)(g_rhT + k * BB + rgB * 8 + 4));
                float4 w0 = *(const float4*)&sWB[k * 8];
                float4 w1 = *(const float4*)&sWB[k * 8 + 4];
                ull hp[4];
                hp[0] = pk2(ha.x, ha.y); hp[1] = pk2(ha.z, ha.w);
                hp[2] = pk2(hb.x, hb.y); hp[3] = pk2(hb.z, hb.w);
                ull wd[8];
                wd[0] = pk2(w0.x, w0.x); wd[1] = pk2(w0.y, w0.y);
                wd[2] = pk2(w0.z, w0.z); wd[3] = pk2(w0.w, w0.w);
                wd[4] = pk2(w1.x, w1.x); wd[5] = pk2(w1.y, w1.y);
                wd[6] = pk2(w1.z, w1.z); wd[7] = pk2(w1.w, w1.w);
#pragma unroll
                for (int rp = 0; rp < 4; rp++)
#pragma unroll
                    for (int c = 0; c < 8; c++) fma2(acc[rp][c], hp[rp], wd[c]);
            }
#pragma unroll
            for (int rp = 0; rp < 4; rp++) {
                int b0 = rgB * 8 + rp * 2;
#pragma unroll
                for (int c = 0; c < 8; c++) {
                    float lo, hi; upk2(acc[rp][c], lo, hi);
                    sred[sB * 576 + b0 * 9 + c] = lo;
                    sred[sB * 576 + (b0 + 1) * 9 + c] = hi;
                }
            }
            __syncthreads();
            const float* __restrict__ xpt = g_xp[2] + (size_t)t * BHN;
            const int n = nbaseB + ocB;
#pragma unroll
            for (int bi = 0; bi < 2; bi++) {
                const int bb = obB + bi;
                float v = 0.0f;
#pragma unroll
                for (int s = 0; s < 32; s++) v += sred[s * 576 + bb * 9 + ocB];
                v += xpt[bb * HH + n];
                float ht = tanhf(v);
                float z  = __ldcg(&g_z[bb * HH + n]);
                float hp = __ldcg(&g_hT[n * BB + bb]);
                float hn = hp + z * (ht - hp);
                out[(size_t)t * BHN + bb * HH + n] = hn;
                g_hT[n * BB + bb] = hn;
            }
        }
        gbar();
    }
}

// ============================================================================
extern "C" void kernel_launch(void* const* d_in, const int* in_sizes, int n_in,
                              void* d_out, int out_size)
{
    const float* x  = (const float*)d_in[0];
    const float* h0 = (const float*)d_in[1];
    const float* Wz = (const float*)d_in[2];
    const float* bz = (const float*)d_in[3];
    const float* Wr = (const float*)d_in[4];
    const float* br = (const float*)d_in[5];
    const float* Wt = (const float*)d_in[6];
    const float* bt = (const float*)d_in[7];
    float* out = (float*)d_out;

    dim3 g1(TT * BB / 128, HH / 64);
    xproj_kernel<<<g1, 256>>>(x, Wz, bz, 0);
    xproj_kernel<<<g1, 256>>>(x, Wr, br, 1);
    xproj_kernel<<<g1, 256>>>(x, Wt, bt, 2);

    const int smem_bytes = 43008 * 4;  // 172032
    cudaFuncSetAttribute(gru_persist, cudaFuncAttributeMaxDynamicSharedMemorySize, smem_bytes);
    gru_persist<<<NCTA, NTHR, smem_bytes>>>(h0, Wz, Wr, Wt, out);
}

// round 3
// speedup vs baseline: 1.0008x; 1.0008x over previous
#include <cuda_runtime.h>
#include <cstdint>
#include <cstddef>

// GRU: T=512, B=64, H=1024, I=1024, fp32.
// Node 1-3: xproj GEMMs (x @ Wg[:,H:]^T + bias) into g_xp.
// Node 4: persistent kernel, 128 CTAs, software grid barriers, 512 steps:
//   Phase A: z = sigmoid(h@Wz[:,:H]^T + xpz); r = sigmoid(h@Wr[:,:H]^T + xpr); rhT = r*h (transposed)
//   Phase B: h~ = tanh(rh@Wt[:,:H]^T + xpt); h = h + z*(h~-h) -> out[t] and hT.

#define TT 512
#define BB 64
#define HH 1024
#define II 1024
#define HIW 2048
#define BHN (BB * HH)            // 65536
#define TBH ((size_t)TT * BHN)
#define NCTA 128
#define NTHR 256

typedef unsigned long long ull;

__device__ float g_xp[3][TBH];   // 402 MB x-projections (+bias)
__device__ float g_hT[HH * BB];  // h transposed [n][b]
__device__ float g_rhT[HH * BB]; // r*h transposed [n][b]
__device__ float g_z[BB * HH];   // z gate [b][n]
__device__ unsigned g_cnt;
__device__ unsigned g_gen;

// ---- packed fp32x2 helpers ----
__device__ __forceinline__ ull pk2(float lo, float hi) {
    ull r; asm("mov.b64 %0, {%1, %2};" : "=l"(r) : "f"(lo), "f"(hi)); return r;
}
__device__ __forceinline__ void upk2(ull v, float& lo, float& hi) {
    asm("mov.b64 {%0, %1}, %2;" : "=f"(lo), "=f"(hi) : "l"(v));
}
__device__ __forceinline__ void fma2(ull& d, ull a, ull b) {
    asm("fma.rn.f32x2 %0, %1, %2, %0;" : "+l"(d) : "l"(a), "l"(b));
}
__device__ __forceinline__ float sigmoidf_fast(float v) {
    return 1.0f / (1.0f + __expf(-v));
}

// Grid-wide sense barrier. All threads fence (release + L1D invalidate on acquire).
__device__ __forceinline__ void gbar() {
    __threadfence();
    __syncthreads();
    if (threadIdx.x == 0) {
        unsigned my = *(volatile unsigned*)&g_gen;
        if (atomicAdd(&g_cnt, 1) == NCTA - 1) {
            g_cnt = 0;
            __threadfence();
            *(volatile unsigned*)&g_gen = my + 1;
        } else {
            while (*(volatile unsigned*)&g_gen == my) { }
        }
    }
    __syncthreads();
    __threadfence();   // acquire; CCTL.IVALL flushes this SM's L1D
}

// ============================================================================
// Phase 1: xproj. C[m,n] = bias[n] + sum_k x[m,k]*W[n,H+k]. M=32768,N=1024,K=1024
// BM=128, BN=64, BK=16, 256 threads, thread tile 8x4.
// ============================================================================
__global__ __launch_bounds__(256) void xproj_kernel(
    const float* __restrict__ x, const float* __restrict__ W,
    const float* __restrict__ bias, int gate)
{
    __shared__ float As[16][132];
    __shared__ float Bs[16][68];

    const int tid = threadIdx.x;
    const int tn = tid & 15;
    const int tm = tid >> 4;
    const int m0 = blockIdx.x * 128;
    const int n0 = blockIdx.y * 64;
    float* __restrict__ out = g_xp[gate];

    ull acc[4][4];
#pragma unroll
    for (int i = 0; i < 4; i++)
#pragma unroll
        for (int j = 0; j < 4; j++) acc[i][j] = 0ull;

    for (int k0 = 0; k0 < II; k0 += 16) {
#pragma unroll
        for (int r = 0; r < 2; r++) {
            int idx = tid + r * 256;
            int mm = idx >> 2;
            int kq = idx & 3;
            float4 v = *(const float4*)(x + (size_t)(m0 + mm) * II + k0 + kq * 4);
            As[kq * 4 + 0][mm] = v.x; As[kq * 4 + 1][mm] = v.y;
            As[kq * 4 + 2][mm] = v.z; As[kq * 4 + 3][mm] = v.w;
        }
        {
            int nn = tid >> 2;
            int kq = tid & 3;
            float4 v = *(const float4*)(W + (size_t)(n0 + nn) * HIW + HH + k0 + kq * 4);
            Bs[kq * 4 + 0][nn] = v.x; Bs[kq * 4 + 1][nn] = v.y;
            Bs[kq * 4 + 2][nn] = v.z; Bs[kq * 4 + 3][nn] = v.w;
        }
        __syncthreads();

#pragma unroll
        for (int k = 0; k < 16; k++) {
            float4 a0 = *(const float4*)&As[k][tm * 8];
            float4 a1 = *(const float4*)&As[k][tm * 8 + 4];
            float4 b  = *(const float4*)&Bs[k][tn * 4];
            ull ap[4];
            ap[0] = pk2(a0.x, a0.y); ap[1] = pk2(a0.z, a0.w);
            ap[2] = pk2(a1.x, a1.y); ap[3] = pk2(a1.z, a1.w);
            ull bs[4];
            bs[0] = pk2(b.x, b.x); bs[1] = pk2(b.y, b.y);
            bs[2] = pk2(b.z, b.z); bs[3] = pk2(b.w, b.w);
#pragma unroll
            for (int rp = 0; rp < 4; rp++)
#pragma unroll
                for (int c = 0; c < 4; c++) fma2(acc[rp][c], ap[rp], bs[c]);
        }
        __syncthreads();
    }

    const float b0 = bias[n0 + tn * 4 + 0];
    const float b1 = bias[n0 + tn * 4 + 1];
    const float b2 = bias[n0 + tn * 4 + 2];
    const float b3 = bias[n0 + tn * 4 + 3];
#pragma unroll
    for (int rp = 0; rp < 4; rp++) {
        float lo[4], hi[4];
#pragma unroll
        for (int c = 0; c < 4; c++) upk2(acc[rp][c], lo[c], hi[c]);
        int row = m0 + tm * 8 + rp * 2;
        float4 vlo = make_float4(lo[0] + b0, lo[1] + b1, lo[2] + b2, lo[3] + b3);
        float4 vhi = make_float4(hi[0] + b0, hi[1] + b1, hi[2] + b2, hi[3] + b3);
        *(float4*)(out + (size_t)row * HH + n0 + tn * 4) = vlo;
        *(float4*)(out + (size_t)(row + 1) * HH + n0 + tn * 4) = vhi;
    }
}

// ============================================================================
// Persistent recurrence kernel. 128 CTAs x 256 threads, 1 CTA/SM.
// Dynamic smem: sWA [1024][16] (64KB) | sWB [1024][8] (32KB) | sred 73728B
// Phase A: CTA<64 -> z cols cta*16..; CTA>=64 -> r cols (cta-64)*16..
//   thread: s=tid>>4 (16 k-slices), cg=(tid>>3)&1 (col half), rg=tid&7 (8-row grp)
//   k = j*16 + s, j=0..63. Tile 8 rows x 8 cols. Reduce 16 partials in smem.
// Phase B: cols cta*8.. ; s=tid>>3 (32 slices), rg=tid&7; k=j*32+s, j=0..31.
// ============================================================================
__global__ __launch_bounds__(NTHR, 1) void gru_persist(
    const float* __restrict__ h0,
    const float* __restrict__ Wz, const float* __restrict__ Wr,
    const float* __restrict__ Wt, float* __restrict__ out)
{
    extern __shared__ float sm[];
    float* sWA  = sm;            // 16384 floats
    float* sWB  = sm + 16384;    // 8192 floats
    float* sred = sm + 24576;    // 18432 floats

    const int tid = threadIdx.x;
    const int cta = blockIdx.x;

    // ---- one-time: load recurrent weight stripes into smem (coalesced in k) ----
    {
        const float* Wsrc = (cta < 64) ? Wz : Wr;
        const int c0 = (cta & 63) * 16;
#pragma unroll 1
        for (int c = 0; c < 16; c++)
            for (int k = tid; k < HH; k += NTHR)
                sWA[k * 16 + c] = Wsrc[(size_t)(c0 + c) * HIW + k];
        const int c0b = cta * 8;
#pragma unroll 1
        for (int c = 0; c < 8; c++)
            for (int k = tid; k < HH; k += NTHR)
                sWB[k * 8 + c] = Wt[(size_t)(c0b + c) * HIW + k];
    }
    // ---- one-time: transpose h0 into g_hT ----
    for (int i = cta * NTHR + tid; i < BHN; i += NCTA * NTHR) {
        int b = i >> 10, n = i & 1023;
        g_hT[n * BB + b] = h0[i];
    }
    __syncthreads();
    gbar();

    const int sA = tid >> 4, cgA = (tid >> 3) & 1, rgA = tid & 7;
    const int sB = tid >> 3, rgB = tid & 7;
    const int ocA = tid & 15; const int obA = (tid >> 4) * 4;
    const int ocB = tid & 7;  const int obB = (tid >> 3) * 2;
    const int gate = (cta < 64) ? 0 : 1;
    const int nbaseA = (cta & 63) * 16;
    const int nbaseB = cta * 8;

    for (int t = 0; t < TT; t++) {
        // ================= Phase A =================
        {
            ull acc[4][8];
#pragma unroll
            for (int i = 0; i < 4; i++)
#pragma unroll
                for (int j = 0; j < 8; j++) acc[i][j] = 0ull;

#pragma unroll 4
            for (int j = 0; j < 64; j++) {
                const int k = j * 16 + sA;
                float4 ha = __ldcg((const float4*)(g_hT + k * BB + rgA * 8));
                float4 hb = __ldcg((const float4*)(g_hT + k * BB + rgA * 8 + 4));
                float4 w0 = *(const float4*)&sWA[k * 16 + cgA * 8];
                float4 w1 = *(const float4*)&sWA[k * 16 + cgA * 8 + 4];
                ull hp[4];
                hp[0] = pk2(ha.x, ha.y); hp[1] = pk2(ha.z, ha.w);
                hp[2] = pk2(hb.x, hb.y); hp[3] = pk2(hb.z, hb.w);
                ull wd[8];
                wd[0] = pk2(w0.x, w0.x); wd[1] = pk2(w0.y, w0.y);
                wd[2] = pk2(w0.z, w0.z); wd[3] = pk2(w0.w, w0.w);
                wd[4] = pk2(w1.x, w1.x); wd[5] = pk2(w1.y, w1.y);
                wd[6] = pk2(w1.z, w1.z); wd[7] = pk2(w1.w, w1.w);
#pragma unroll
                for (int rp = 0; rp < 4; rp++)
#pragma unroll
                    for (int c = 0; c < 8; c++) fma2(acc[rp][c], hp[rp], wd[c]);
            }
            // write partials
#pragma unroll
            for (int rp = 0; rp < 4; rp++) {
                int b0 = rgA * 8 + rp * 2;
#pragma unroll
                for (int c = 0; c < 8; c++) {
                    float lo, hi; upk2(acc[rp][c], lo, hi);
                    sred[sA * 1152 + b0 * 18 + cgA * 8 + c] = lo;
                    sred[sA * 1152 + (b0 + 1) * 18 + cgA * 8 + c] = hi;
                }
            }
            __syncthreads();
            // reduce 16 partials + epilogue (4 outputs/thread)
            const float* __restrict__ xpg = g_xp[gate] + (size_t)t * BHN;
            const int n = nbaseA + ocA;
#pragma unroll
            for (int bi = 0; bi < 4; bi++) {
                const int bb = obA + bi;
                float v = 0.0f;
#pragma unroll
                for (int s = 0; s < 16; s++) v += sred[s * 1152 + bb * 18 + ocA];
                v += xpg[bb * HH + n];
                float sg = sigmoidf_fast(v);
                if (gate == 0) {
                    g_z[bb * HH + n] = sg;
                } else {
                    float hp = __ldcg(&g_hT[n * BB + bb]);
                    g_rhT[n * BB + bb] = sg * hp;
                }
            }
        }
        gbar();

        // ================= Phase B =================
        {
            ull acc[4][8];
#pragma unroll
            for (int i = 0; i < 4; i++)
#pragma unroll
                for (int j = 0; j < 8; j++) acc[i][j] = 0ull;

#pragma unroll 4
            for (int j = 0; j < 32; j++) {
                const int k = j * 32 + sB;
                float4 ha = __ldcg((const float4*)(g_rhT + k * BB + rgB * 8));
                float4 hb = __ldcg((const float4*)(g_rhT + k * BB + rgB * 8 + 4));
                float4 w0 = *(const float4*)&sWB[k * 8];
                float4 w1 = *(const float4*)&sWB[k * 8 + 4];
                ull hp[4];
                hp[0] = pk2(ha.x, ha.y); hp[1] = pk2(ha.z, ha.w);
                hp[2] = pk2(hb.x, hb.y); hp[3] = pk2(hb.z, hb.w);
                ull wd[8];
                wd[0] = pk2(w0.x, w0.x); wd[1] = pk2(w0.y, w0.y);
                wd[2] = pk2(w0.z, w0.z); wd[3] = pk2(w0.w, w0.w);
                wd[4] = pk2(w1.x, w1.x); wd[5] = pk2(w1.y, w1.y);
                wd[6] = pk2(w1.z, w1.z); wd[7] = pk2(w1.w, w1.w);
#pragma unroll
                for (int rp = 0; rp < 4; rp++)
#pragma unroll
                    for (int c = 0; c < 8; c++) fma2(acc[rp][c], hp[rp], wd[c]);
            }
#pragma unroll
            for (int rp = 0; rp < 4; rp++) {
                int b0 = rgB * 8 + rp * 2;
#pragma unroll
                for (int c = 0; c < 8; c++) {
                    float lo, hi; upk2(acc[rp][c], lo, hi);
                    sred[sB * 576 + b0 * 9 + c] = lo;
                    sred[sB * 576 + (b0 + 1) * 9 + c] = hi;
                }
            }
            __syncthreads();
            const float* __restrict__ xpt = g_xp[2] + (size_t)t * BHN;
            const int n = nbaseB + ocB;
#pragma unroll
            for (int bi = 0; bi < 2; bi++) {
                const int bb = obB + bi;
                float v = 0.0f;
#pragma unroll
                for (int s = 0; s < 32; s++) v += sred[s * 576 + bb * 9 + ocB];
                v += xpt[bb * HH + n];
                float ht = tanhf(v);
                float z  = __ldcg(&g_z[bb * HH + n]);
                float hp = __ldcg(&g_hT[n * BB + bb]);
                float hn = hp + z * (ht - hp);
                out[(size_t)t * BHN + bb * HH + n] = hn;
                g_hT[n * BB + bb] = hn;
            }
        }
        gbar();
    }
}

// ============================================================================
extern "C" void kernel_launch(void* const* d_in, const int* in_sizes, int n_in,
                              void* d_out, int out_size)
{
    const float* x  = (const float*)d_in[0];
    const float* h0 = (const float*)d_in[1];
    const float* Wz = (const float*)d_in[2];
    const float* bz = (const float*)d_in[3];
    const float* Wr = (const float*)d_in[4];
    const float* br = (const float*)d_in[5];
    const float* Wt = (const float*)d_in[6];
    const float* bt = (const float*)d_in[7];
    float* out = (float*)d_out;

    dim3 g1(TT * BB / 128, HH / 64);
    xproj_kernel<<<g1, 256>>>(x, Wz, bz, 0);
    xproj_kernel<<<g1, 256>>>(x, Wr, br, 1);
    xproj_kernel<<<g1, 256>>>(x, Wt, bt, 2);

    const int smem_bytes = 43008 * 4;  // 172032
    cudaFuncSetAttribute(gru_persist, cudaFuncAttributeMaxDynamicSharedMemorySize, smem_bytes);
    gru_persist<<<NCTA, NTHR, smem_bytes>>>(h0, Wz, Wr, Wt, out);
}